// round 6
// baseline (speedup 1.0000x reference)
#include <cuda_runtime.h>
#include <cstdint>

// Problem constants (fixed by setup_inputs): B=32, T_src=1024, H=512.
#define B_DIM 32
#define T_SRC 1024
#define H_DIM 512

// Scratch: cumulative durations per batch + totals. __device__ globals (no alloc).
__device__ int g_cum[B_DIM * T_SRC];
__device__ int g_tot[B_DIM];

// Kernel 1: per-batch inclusive scan of durations (Hillis-Steele, 1024 threads).
__global__ void lr_cumsum_kernel(const int* __restrict__ dur) {
    __shared__ int s[T_SRC];
    const int b = blockIdx.x;
    const int t = threadIdx.x;
    s[t] = dur[b * T_SRC + t];
    __syncthreads();
#pragma unroll
    for (int off = 1; off < T_SRC; off <<= 1) {
        int v = (t >= off) ? s[t - off] : 0;
        __syncthreads();
        s[t] += v;
        __syncthreads();
    }
    g_cum[b * T_SRC + t] = s[t];
    if (t == T_SRC - 1) g_tot[b] = s[t];
}

// Kernel 2: one block per output row (b, t). 128 threads copy 512 floats as float4.
// searchsorted(c, t, side='right') over the cum row finds the source frame;
// rows past the batch total are zero-filled and masked.
// NOTE: answer space is [0, T_SRC] (1025 values) -> needs up to 11 halving
// steps; the while-loop form is exact (the previous fixed-10-step unroll was
// off by one on the all-left path).
__global__ void __launch_bounds__(128) lr_expand_kernel(
    const float* __restrict__ x,
    float* __restrict__ out,
    float* __restrict__ mask,
    int max_len)
{
    const int t = blockIdx.x;
    const int b = blockIdx.y;
    const int lane = threadIdx.x;

    const int* __restrict__ c = g_cum + b * T_SRC;
    const int total = g_tot[b];
    const bool pad = (t >= total);

    // first s with c[s] > t   (== searchsorted side='right')
    int lo = 0, hi = T_SRC;
    while (lo < hi) {                 // <=11 iterations, uniform per block
        int mid = (lo + hi) >> 1;
        if (__ldg(&c[mid]) <= t) lo = mid + 1; else hi = mid;
    }
    int idx = lo < (T_SRC - 1) ? lo : (T_SRC - 1);

    const float4* __restrict__ src =
        reinterpret_cast<const float4*>(x + ((size_t)b * T_SRC + idx) * H_DIM);
    float4* __restrict__ dst =
        reinterpret_cast<float4*>(out + ((size_t)b * max_len + t) * H_DIM);

    // H_DIM/4 = 128 float4 per row == blockDim.x
    dst[lane] = pad ? make_float4(0.f, 0.f, 0.f, 0.f) : src[lane];

    if (lane == 0) mask[(size_t)b * max_len + t] = pad ? 1.0f : 0.0f;
}

extern "C" void kernel_launch(void* const* d_in, const int* in_sizes, int n_in,
                              void* d_out, int out_size) {
    const float* x   = (const float*)d_in[0];
    const int*   dur = (const int*)d_in[1];
    float* out = (float*)d_out;

    // out_size = B*max_len*H + B*max_len = B*max_len*(H+1)
    const int max_len = out_size / (B_DIM * (H_DIM + 1));
    float* mask = out + (size_t)B_DIM * max_len * H_DIM;

    lr_cumsum_kernel<<<B_DIM, T_SRC>>>(dur);

    dim3 grid(max_len, B_DIM);
    lr_expand_kernel<<<grid, 128>>>(x, out, mask, max_len);
}

// round 7
// speedup vs baseline: 2.4271x; 2.4271x over previous
#include <cuda_runtime.h>
#include <cstdint>

// Problem constants (fixed by setup_inputs): B=32, T_src=1024, H=512.
#define B_DIM 32
#define T_SRC 1024
#define H_DIM 512
#define MAX_EXP (T_SRC * 7)   // durations in [0,8) -> max total = 7*1024
#define ROWS 4                // output rows per expand block

// Scratch (__device__ globals, no allocation):
__device__ int g_tot[B_DIM];
__device__ int g_idx[B_DIM * MAX_EXP];  // source-frame index per output row

// Kernel 1: per-batch inclusive scan of durations (Hillis-Steele, 1024 thr),
// FUSED with the inverse-map scatter: each source frame s owns output range
// [cum[s-1], cum[s]) (at most 7 slots) and writes idx=s there. This replaces
// the per-output-row binary search entirely.
__global__ void lr_scan_scatter_kernel(const int* __restrict__ dur, int max_len) {
    __shared__ int s[T_SRC];
    const int b = blockIdx.x;
    const int t = threadIdx.x;
    s[t] = dur[b * T_SRC + t];
    __syncthreads();
#pragma unroll
    for (int off = 1; off < T_SRC; off <<= 1) {
        int v = (t >= off) ? s[t - off] : 0;
        __syncthreads();
        s[t] += v;
        __syncthreads();
    }
    const int end   = s[t];
    const int start = (t > 0) ? s[t - 1] : 0;
    int* __restrict__ irow = g_idx + b * max_len;
    for (int j = start; j < end; ++j) irow[j] = t;   // <=7 iterations
    if (t == T_SRC - 1) g_tot[b] = end;
}

// Kernel 2: 4 output rows per block, 128 threads. Pure gather-copy:
// per row one broadcast idx load, then batched independent LDG.128 followed
// by streaming STG.128 (keep x resident in L2; output is write-once).
__global__ void __launch_bounds__(128) lr_expand_kernel(
    const float* __restrict__ x,
    float* __restrict__ out,
    float* __restrict__ mask,
    int max_len)
{
    const int t0   = blockIdx.x * ROWS;
    const int b    = blockIdx.y;
    const int lane = threadIdx.x;

    const int total = g_tot[b];
    const int* __restrict__ irow = g_idx + (size_t)b * max_len;
    const float4* __restrict__ xb =
        reinterpret_cast<const float4*>(x + (size_t)b * T_SRC * H_DIM);
    float4* __restrict__ ob =
        reinterpret_cast<float4*>(out + (size_t)b * max_len * H_DIM);

    // Phase 1: row indices (broadcast loads, independent).
    int idx[ROWS];
#pragma unroll
    for (int r = 0; r < ROWS; ++r) {
        int t = t0 + r;
        idx[r] = (t < max_len && t < total) ? __ldg(&irow[t]) : -1;
    }

    // Phase 2: batched gathers (MLP = ROWS).
    float4 v[ROWS];
#pragma unroll
    for (int r = 0; r < ROWS; ++r) {
        v[r] = (idx[r] >= 0)
                 ? __ldg(&xb[(size_t)idx[r] * (H_DIM / 4) + lane])
                 : make_float4(0.f, 0.f, 0.f, 0.f);
    }

    // Phase 3: streaming stores (H_DIM/4 == 128 == blockDim.x).
#pragma unroll
    for (int r = 0; r < ROWS; ++r) {
        int t = t0 + r;
        if (t < max_len)
            __stcs(&ob[(size_t)t * (H_DIM / 4) + lane], v[r]);
    }

    // Mask: lanes 0..ROWS-1 write one row each.
    if (lane < ROWS) {
        int t = t0 + lane;
        if (t < max_len)
            mask[(size_t)b * max_len + t] = (t >= total) ? 1.0f : 0.0f;
    }
}

extern "C" void kernel_launch(void* const* d_in, const int* in_sizes, int n_in,
                              void* d_out, int out_size) {
    const float* x   = (const float*)d_in[0];
    const int*   dur = (const int*)d_in[1];
    float* out = (float*)d_out;

    // out_size = B*max_len*H + B*max_len = B*max_len*(H+1)
    const int max_len = out_size / (B_DIM * (H_DIM + 1));
    float* mask = out + (size_t)B_DIM * max_len * H_DIM;

    lr_scan_scatter_kernel<<<B_DIM, T_SRC>>>(dur, max_len);

    dim3 grid((max_len + ROWS - 1) / ROWS, B_DIM);
    lr_expand_kernel<<<grid, 128>>>(x, out, mask, max_len);
}

// round 8
// speedup vs baseline: 2.4504x; 1.0096x over previous
#include <cuda_runtime.h>
#include <cstdint>

// Problem constants (fixed by setup_inputs): B=32, T_src=1024, H=512.
#define B_DIM 32
#define T_SRC 1024
#define H_DIM 512
#define MAX_EXP (T_SRC * 7)   // durations in [0,8) -> max total = 7*1024
#define ROWS 8                // output rows per expand block

// Scratch (__device__ globals, no allocation):
__device__ int g_tot[B_DIM];
__device__ int g_idx[B_DIM * MAX_EXP];  // source-frame index per output row

// Kernel 1: per-batch inclusive scan of durations via warp shuffles
// (5 SHFL warp scan + warp-sum scan; 2 barriers instead of 20), fused with
// the inverse-map scatter: source frame s owns output range [cum[s-1], cum[s])
// (<=7 slots) and writes idx=s there.
__global__ void lr_scan_scatter_kernel(const int* __restrict__ dur, int max_len) {
    __shared__ int warp_sums[32];
    const int b = blockIdx.x;
    const int t = threadIdx.x;
    const int lane = t & 31;
    const int wid  = t >> 5;

    const int v = dur[b * T_SRC + t];

    // Inclusive scan within warp.
    int sc = v;
#pragma unroll
    for (int off = 1; off < 32; off <<= 1) {
        int n = __shfl_up_sync(0xffffffffu, sc, off);
        if (lane >= off) sc += n;
    }
    if (lane == 31) warp_sums[wid] = sc;
    __syncthreads();

    // Warp 0 scans the 32 warp totals.
    if (wid == 0) {
        int ws = warp_sums[lane];
#pragma unroll
        for (int off = 1; off < 32; off <<= 1) {
            int n = __shfl_up_sync(0xffffffffu, ws, off);
            if (lane >= off) ws += n;
        }
        warp_sums[lane] = ws;
    }
    __syncthreads();

    const int base  = (wid > 0) ? warp_sums[wid - 1] : 0;
    const int end   = base + sc;
    const int start = end - v;

    int* __restrict__ irow = g_idx + (size_t)b * max_len;
    for (int j = start; j < end; ++j) irow[j] = t;   // <=7 iterations
    if (t == T_SRC - 1) g_tot[b] = end;
}

// Kernel 2: 8 output rows per block, 128 threads. Pure gather-copy:
// batched broadcast idx loads, then 8 independent LDG.128 (MLP=8), then
// 8 streaming STG.128 (keep x resident in L2; output is write-once).
__global__ void __launch_bounds__(128) lr_expand_kernel(
    const float* __restrict__ x,
    float* __restrict__ out,
    float* __restrict__ mask,
    int max_len)
{
    const int t0   = blockIdx.x * ROWS;
    const int b    = blockIdx.y;
    const int lane = threadIdx.x;

    const int total = g_tot[b];
    const int* __restrict__ irow = g_idx + (size_t)b * max_len;
    const float4* __restrict__ xb =
        reinterpret_cast<const float4*>(x + (size_t)b * T_SRC * H_DIM);
    float4* __restrict__ ob =
        reinterpret_cast<float4*>(out + (size_t)b * max_len * H_DIM);

    // Phase 1: row indices (broadcast loads, independent).
    int idx[ROWS];
#pragma unroll
    for (int r = 0; r < ROWS; ++r) {
        int t = t0 + r;
        idx[r] = (t < max_len && t < total) ? __ldg(&irow[t]) : -1;
    }

    // Phase 2: batched gathers (MLP = ROWS).
    float4 v[ROWS];
#pragma unroll
    for (int r = 0; r < ROWS; ++r) {
        v[r] = (idx[r] >= 0)
                 ? __ldg(&xb[(size_t)idx[r] * (H_DIM / 4) + lane])
                 : make_float4(0.f, 0.f, 0.f, 0.f);
    }

    // Phase 3: streaming stores (H_DIM/4 == 128 == blockDim.x).
#pragma unroll
    for (int r = 0; r < ROWS; ++r) {
        int t = t0 + r;
        if (t < max_len)
            __stcs(&ob[(size_t)t * (H_DIM / 4) + lane], v[r]);
    }

    // Mask: lanes 0..ROWS-1 write one row each.
    if (lane < ROWS) {
        int t = t0 + lane;
        if (t < max_len)
            mask[(size_t)b * max_len + t] = (t >= total) ? 1.0f : 0.0f;
    }
}

extern "C" void kernel_launch(void* const* d_in, const int* in_sizes, int n_in,
                              void* d_out, int out_size) {
    const float* x   = (const float*)d_in[0];
    const int*   dur = (const int*)d_in[1];
    float* out = (float*)d_out;

    // out_size = B*max_len*H + B*max_len = B*max_len*(H+1)
    const int max_len = out_size / (B_DIM * (H_DIM + 1));
    float* mask = out + (size_t)B_DIM * max_len * H_DIM;

    lr_scan_scatter_kernel<<<B_DIM, T_SRC>>>(dur, max_len);

    dim3 grid((max_len + ROWS - 1) / ROWS, B_DIM);
    lr_expand_kernel<<<grid, 128>>>(x, out, mask, max_len);
}

// round 9
// speedup vs baseline: 2.4562x; 1.0024x over previous
#include <cuda_runtime.h>
#include <cstdint>

// Problem constants (fixed by setup_inputs): B=32, T_src=1024, H=512.
#define B_DIM 32
#define T_SRC 1024
#define H_DIM 512
#define MAX_EXP (T_SRC * 7)   // durations in [0,8) -> max total = 7*1024
#define ROWS 8                // output rows per expand block
#define CHUNKS 8              // scatter chunks per batch (kernel 1 grid.x)

// Scratch (__device__ globals, no allocation):
__device__ int g_tot[B_DIM];
__device__ int g_idx[B_DIM * MAX_EXP];  // source-frame index per output row

// Kernel 1: grid (CHUNKS, B), 128 threads. Every block redundantly scans the
// full 1024-duration row for its batch (thread-sequential 8 + warp shuffle
// scan + cross-warp combine; the 4KB row is L2-resident for the redundant
// blocks), then scatters ONLY its 128-frame chunk: frame f owns output range
// [cum[f-1], cum[f]) (<=7 slots) and writes idx=f there. 256 blocks instead
// of 32 -> scatter is no longer serialized on 32 SMs.
__global__ void __launch_bounds__(128) lr_scan_scatter_kernel(
    const int* __restrict__ dur, int max_len)
{
    __shared__ int s_cum[T_SRC];
    __shared__ int s_wsum[4];
    const int chunk = blockIdx.x;
    const int b     = blockIdx.y;
    const int t     = threadIdx.x;        // 0..127
    const int lane  = t & 31;
    const int wid   = t >> 5;

    // Load 8 consecutive durations (two int4 loads, fully coalesced).
    const int4* dr = reinterpret_cast<const int4*>(dur + b * T_SRC + t * 8);
    int4 d0 = __ldg(&dr[0]);
    int4 d1 = __ldg(&dr[1]);
    int e[8] = {d0.x, d0.y, d0.z, d0.w, d1.x, d1.y, d1.z, d1.w};

    // Sequential inclusive prefix over this thread's 8 elements.
    int pre[8];
    int run = 0;
#pragma unroll
    for (int j = 0; j < 8; ++j) { run += e[j]; pre[j] = run; }

    // Warp-inclusive scan of per-thread sums.
    int sc = run;
#pragma unroll
    for (int off = 1; off < 32; off <<= 1) {
        int n = __shfl_up_sync(0xffffffffu, sc, off);
        if (lane >= off) sc += n;
    }
    if (lane == 31) s_wsum[wid] = sc;
    __syncthreads();

    int base = 0;
#pragma unroll
    for (int w = 0; w < 4; ++w) base += (w < wid) ? s_wsum[w] : 0;
    const int thread_base = base + sc - run;

#pragma unroll
    for (int j = 0; j < 8; ++j) s_cum[t * 8 + j] = thread_base + pre[j];
    __syncthreads();

    // Scatter this block's 128-frame chunk.
    const int f     = chunk * 128 + t;
    const int end   = s_cum[f];
    const int start = (f > 0) ? s_cum[f - 1] : 0;
    int* __restrict__ irow = g_idx + (size_t)b * max_len;
    for (int j = start; j < end; ++j) irow[j] = f;   // <=7 iterations

    if (chunk == 0 && t == 0) g_tot[b] = s_cum[T_SRC - 1];
}

// Kernel 2: 8 output rows per block, 128 threads, software-pipelined so only
// 4 row buffers live at once (regs ~40 -> higher occupancy than holding 8).
// Broadcast idx loads, independent LDG.128 gathers (x stays L2-resident),
// streaming STG.128 for the write-once output.
__global__ void __launch_bounds__(128) lr_expand_kernel(
    const float* __restrict__ x,
    float* __restrict__ out,
    float* __restrict__ mask,
    int max_len)
{
    const int t0   = blockIdx.x * ROWS;
    const int b    = blockIdx.y;
    const int lane = threadIdx.x;

    const int total = g_tot[b];
    const int* __restrict__ irow = g_idx + (size_t)b * max_len;
    const float4* __restrict__ xb =
        reinterpret_cast<const float4*>(x + (size_t)b * T_SRC * H_DIM);
    float4* __restrict__ ob =
        reinterpret_cast<float4*>(out + (size_t)b * max_len * H_DIM);

    // Row indices (broadcast loads, independent).
    int idx[ROWS];
#pragma unroll
    for (int r = 0; r < ROWS; ++r) {
        int t = t0 + r;
        idx[r] = (t < max_len && t < total) ? __ldg(&irow[t]) : -1;
    }

    // Pipeline: gather rows 0-3, then {gather r+4, store r}, then store 4-7.
    float4 v[4];
#pragma unroll
    for (int r = 0; r < 4; ++r) {
        v[r] = (idx[r] >= 0)
                 ? __ldg(&xb[(size_t)idx[r] * (H_DIM / 4) + lane])
                 : make_float4(0.f, 0.f, 0.f, 0.f);
    }
#pragma unroll
    for (int r = 0; r < 4; ++r) {
        float4 nv = (idx[r + 4] >= 0)
                 ? __ldg(&xb[(size_t)idx[r + 4] * (H_DIM / 4) + lane])
                 : make_float4(0.f, 0.f, 0.f, 0.f);
        int t = t0 + r;
        if (t < max_len)
            __stcs(&ob[(size_t)t * (H_DIM / 4) + lane], v[r]);
        v[r] = nv;
    }
#pragma unroll
    for (int r = 0; r < 4; ++r) {
        int t = t0 + 4 + r;
        if (t < max_len)
            __stcs(&ob[(size_t)t * (H_DIM / 4) + lane], v[r]);
    }

    // Mask: lanes 0..ROWS-1 write one row each.
    if (lane < ROWS) {
        int t = t0 + lane;
        if (t < max_len)
            mask[(size_t)b * max_len + t] = (t >= total) ? 1.0f : 0.0f;
    }
}

extern "C" void kernel_launch(void* const* d_in, const int* in_sizes, int n_in,
                              void* d_out, int out_size) {
    const float* x   = (const float*)d_in[0];
    const int*   dur = (const int*)d_in[1];
    float* out = (float*)d_out;

    // out_size = B*max_len*H + B*max_len = B*max_len*(H+1)
    const int max_len = out_size / (B_DIM * (H_DIM + 1));
    float* mask = out + (size_t)B_DIM * max_len * H_DIM;

    dim3 g1(CHUNKS, B_DIM);
    lr_scan_scatter_kernel<<<g1, 128>>>(dur, max_len);

    dim3 g2((max_len + ROWS - 1) / ROWS, B_DIM);
    lr_expand_kernel<<<g2, 128>>>(x, out, mask, max_len);
}

// round 10
// speedup vs baseline: 2.5574x; 1.0412x over previous
#include <cuda_runtime.h>
#include <cstdint>

// Problem constants (fixed by setup_inputs): B=32, T_src=1024, H=512.
#define B_DIM 32
#define T_SRC 1024
#define H_DIM 512
#define ROWS 8   // output rows per block

// SINGLE fused kernel: grid (ceil(max_len/8), B), 128 threads.
// Prologue (per block, cheap & hidden): load this batch's 1024 durations
// (L2-resident, 2x int4 per thread), inclusive scan into SMEM (sequential-8 +
// warp shuffle + cross-warp combine), then 8 threads binary-search the 8
// output rows' source frames in SMEM. Body: R8-style batched gather/store —
// 8 independent LDG.128 (MLP=8, x stays L2-resident) then 8 streaming
// STG.128 for the write-once output. No scratch globals, no second launch,
// no g_idx round-trip.
__global__ void __launch_bounds__(128) lr_fused_kernel(
    const float* __restrict__ x,
    const int*  __restrict__ dur,
    float* __restrict__ out,
    float* __restrict__ mask,
    int max_len)
{
    __shared__ int s_cum[T_SRC];
    __shared__ int s_wsum[4];
    __shared__ int s_idx[ROWS];

    const int t0   = blockIdx.x * ROWS;
    const int b    = blockIdx.y;
    const int tid  = threadIdx.x;        // 0..127
    const int lane = tid & 31;
    const int wid  = tid >> 5;

    // ---- Prologue: scan durations[b, :] into s_cum ----
    {
        const int4* dr = reinterpret_cast<const int4*>(dur + b * T_SRC + tid * 8);
        int4 d0 = __ldg(&dr[0]);
        int4 d1 = __ldg(&dr[1]);
        int e0 = d0.x, e1 = d0.y, e2 = d0.z, e3 = d0.w;
        int e4 = d1.x, e5 = d1.y, e6 = d1.z, e7 = d1.w;

        int p0 = e0, p1 = p0 + e1, p2 = p1 + e2, p3 = p2 + e3;
        int p4 = p3 + e4, p5 = p4 + e5, p6 = p5 + e6, p7 = p6 + e7;

        int sc = p7;  // this thread's total
#pragma unroll
        for (int off = 1; off < 32; off <<= 1) {
            int n = __shfl_up_sync(0xffffffffu, sc, off);
            if (lane >= off) sc += n;
        }
        if (lane == 31) s_wsum[wid] = sc;
        __syncthreads();

        int base = 0;
#pragma unroll
        for (int w = 0; w < 4; ++w) base += (w < wid) ? s_wsum[w] : 0;
        const int tb = base + sc - p7;

        int* c = s_cum + tid * 8;
        c[0] = tb + p0; c[1] = tb + p1; c[2] = tb + p2; c[3] = tb + p3;
        c[4] = tb + p4; c[5] = tb + p5; c[6] = tb + p6; c[7] = tb + p7;
    }
    __syncthreads();

    const int total = s_cum[T_SRC - 1];

    // ---- 8 searchsorted lookups (threads 0..7), results broadcast via SMEM ----
    if (tid < ROWS) {
        int t = t0 + tid;
        int idx = -1;
        if (t < max_len && t < total) {
            int lo = 0, hi = T_SRC;          // first s with cum[s] > t
            while (lo < hi) {
                int mid = (lo + hi) >> 1;
                if (s_cum[mid] <= t) lo = mid + 1; else hi = mid;
            }
            idx = lo < (T_SRC - 1) ? lo : (T_SRC - 1);
        }
        s_idx[tid] = idx;
    }
    __syncthreads();

    // ---- Body: batched gather (MLP=8) + streaming stores ----
    int idx[ROWS];
#pragma unroll
    for (int r = 0; r < ROWS; ++r) idx[r] = s_idx[r];

    const float4* __restrict__ xb =
        reinterpret_cast<const float4*>(x + (size_t)b * T_SRC * H_DIM);
    float4* __restrict__ ob =
        reinterpret_cast<float4*>(out + (size_t)b * max_len * H_DIM);

    float4 v[ROWS];
#pragma unroll
    for (int r = 0; r < ROWS; ++r) {
        v[r] = (idx[r] >= 0)
                 ? __ldg(&xb[(size_t)idx[r] * (H_DIM / 4) + tid])
                 : make_float4(0.f, 0.f, 0.f, 0.f);
    }
#pragma unroll
    for (int r = 0; r < ROWS; ++r) {
        int t = t0 + r;
        if (t < max_len)
            __stcs(&ob[(size_t)t * (H_DIM / 4) + tid], v[r]);
    }

    // Mask: lanes 0..ROWS-1 write one row each.
    if (tid < ROWS) {
        int t = t0 + tid;
        if (t < max_len)
            mask[(size_t)b * max_len + t] = (t >= total) ? 1.0f : 0.0f;
    }
}

extern "C" void kernel_launch(void* const* d_in, const int* in_sizes, int n_in,
                              void* d_out, int out_size) {
    const float* x   = (const float*)d_in[0];
    const int*   dur = (const int*)d_in[1];
    float* out = (float*)d_out;

    // out_size = B*max_len*H + B*max_len = B*max_len*(H+1)
    const int max_len = out_size / (B_DIM * (H_DIM + 1));
    float* mask = out + (size_t)B_DIM * max_len * H_DIM;

    dim3 grid((max_len + ROWS - 1) / ROWS, B_DIM);
    lr_fused_kernel<<<grid, 128>>>(x, dur, out, mask, max_len);
}